// round 1
// baseline (speedup 1.0000x reference)
#include <cuda_runtime.h>
#include <math.h>
#include <stdint.h>

#define SEQL 256
#define BATCH 64
#define HID 1024
#define GATES 4096
#define MROWS (SEQL*BATCH)      // 16384
#define BH (BATCH*HID)          // 65536

// ---------------- scratch (device globals; no cudaMalloc allowed) ----------
__device__ float g_xp[(size_t)MROWS * GATES];   // 256 MB: x-projection for one layer
__device__ float g_ys[(size_t)SEQL * BH];       // 64 MB: layer-0 h history (input to layer 1)
__device__ float g_hb[2 * BH];                  // layer-1 h ping-pong
__device__ volatile unsigned g_bar_gen;
__device__ unsigned g_bar_cnt;

// ---------------- grid barrier (all blocks resident: 128 blocks, 1/SM) -----
__device__ __forceinline__ void gridbar(unsigned nblk) {
    __threadfence();
    __syncthreads();
    if (threadIdx.x == 0) {
        unsigned gen = g_bar_gen;
        if (atomicAdd(&g_bar_cnt, 1u) == nblk - 1u) {
            atomicExch(&g_bar_cnt, 0u);
            __threadfence();
            g_bar_gen = gen + 1u;
        } else {
            while (g_bar_gen == gen) { __nanosleep(32); }
            __threadfence();
        }
    }
    __syncthreads();
}

// ---------------- SGEMM: C[M][4096] = gather(A)[M][1024] @ W[4096][1024]^T + b1 + b2
// block tile 128x128, BK=16, 256 threads, 8x8 per-thread tile
__global__ __launch_bounds__(256) void sgemm_xp(
    const float* __restrict__ A, const int* __restrict__ gidx,
    const float* __restrict__ W,
    const float* __restrict__ b1, const float* __restrict__ b2,
    float* __restrict__ C)
{
    __shared__ float As[16][132];
    __shared__ float Ws[16][132];
    const int bn = blockIdx.x * 128;
    const int bm = blockIdx.y * 128;
    const int tid = threadIdx.x;
    const int tr = tid >> 4;       // 0..15
    const int tc = tid & 15;       // 0..15

    float acc[8][8];
#pragma unroll
    for (int i = 0; i < 8; i++)
#pragma unroll
        for (int j = 0; j < 8; j++) acc[i][j] = 0.f;

    for (int kc = 0; kc < 1024; kc += 16) {
#pragma unroll
        for (int rep = 0; rep < 2; rep++) {
            int q = tid + rep * 256;          // 0..511
            int row = q >> 2;                 // 0..127
            int c4  = q & 3;                  // float4 index within 16-wide k chunk
            int grow = bm + row;
            int arow = gidx ? gidx[grow] : grow;
            float4 v = *(const float4*)(A + (size_t)arow * 1024 + kc + c4 * 4);
            As[c4*4+0][row] = v.x; As[c4*4+1][row] = v.y;
            As[c4*4+2][row] = v.z; As[c4*4+3][row] = v.w;
            int wrow = bn + row;
            float4 wv = *(const float4*)(W + (size_t)wrow * 1024 + kc + c4 * 4);
            Ws[c4*4+0][row] = wv.x; Ws[c4*4+1][row] = wv.y;
            Ws[c4*4+2][row] = wv.z; Ws[c4*4+3][row] = wv.w;
        }
        __syncthreads();
#pragma unroll
        for (int k = 0; k < 16; k++) {
            alignas(16) float a[8];
            alignas(16) float w[8];
            *(float4*)&a[0] = *(const float4*)&As[k][tr*8];
            *(float4*)&a[4] = *(const float4*)&As[k][tr*8+4];
            *(float4*)&w[0] = *(const float4*)&Ws[k][tc*8];
            *(float4*)&w[4] = *(const float4*)&Ws[k][tc*8+4];
#pragma unroll
            for (int i = 0; i < 8; i++)
#pragma unroll
                for (int j = 0; j < 8; j++)
                    acc[i][j] += a[i] * w[j];
        }
        __syncthreads();
    }

#pragma unroll
    for (int i = 0; i < 8; i++) {
        int m = bm + tr*8 + i;
#pragma unroll
        for (int j = 0; j < 8; j++) {
            int n = bn + tc*8 + j;
            C[(size_t)m * GATES + n] = acc[i][j] + b1[n] + b2[n];
        }
    }
}

// ---------------- persistent LSTM recurrence -------------------------------
// 128 blocks x 128 threads. Block b owns j in [j0, j0+8). Weights for its 32
// gate-columns (4 gates x 8 j) preloaded to SMEM once. c-state in SMEM.
// mode 0: h history in hist[t*BH] (layer 0, also serves as ys output)
// mode 1: h ping-pong in hist[(t&1)*BH]
#define REC_SMEM ((1024*32 + 64*64 + 64*33 + 8*64) * 4)

__global__ __launch_bounds__(128, 1) void lstm_rec(
    const float* __restrict__ xp, const float* __restrict__ whh,
    float* hist, int mode, float* __restrict__ out_h, float* __restrict__ out_c)
{
    extern __shared__ float sm[];
    float* ws  = sm;                    // [1024][32]  ws[k*32+c]
    float* hs  = ws  + 1024*32;         // [64][64]    hs[k*64+b]
    float* gsm = hs  + 64*64;           // [64][33]    gsm[b*33+c]
    float* cst = gsm + 64*33;           // [8][64]     cst[jj*64+b]

    const int tid = threadIdx.x;
    const int j0  = blockIdx.x * 8;
    const unsigned nblk = gridDim.x;

    // preload this block's 32 weight rows: row(c) = (c/8)*1024 + j0 + (c%8)
    {
        int c  = tid & 31;
        int kq = tid >> 5;                       // 0..3, each owns 256 k's
        int wrow = ((c >> 3) << 10) + j0 + (c & 7);
        const float4* w4 = (const float4*)(whh + (size_t)wrow * 1024);
        for (int k4 = kq*64; k4 < kq*64 + 64; k4++) {
            float4 v = w4[k4];
            int k = k4 * 4;
            ws[(k+0)*32 + c] = v.x; ws[(k+1)*32 + c] = v.y;
            ws[(k+2)*32 + c] = v.z; ws[(k+3)*32 + c] = v.w;
        }
    }
    for (int q = tid; q < 512; q += 128) cst[q] = 0.f;
    __syncthreads();

    const int c0 = (tid & 7) * 4;    // gate-col tile base (0..28)
    const int b0 = (tid >> 3) * 4;   // batch tile base (0..60)

    for (int t = 0; t < SEQL; t++) {
        float acc[4][4];
#pragma unroll
        for (int i = 0; i < 4; i++)
#pragma unroll
            for (int j = 0; j < 4; j++) acc[i][j] = 0.f;

        if (t > 0) {
            const float* hp = (mode == 0) ? hist + (size_t)(t-1) * BH
                                          : hist + (size_t)((t-1) & 1) * BH;
            for (int kc = 0; kc < 1024; kc += 64) {
                // stage h chunk transposed: hs[k][b]
                {
                    int b = tid & 63, half = tid >> 6;
                    const float4* h4 = (const float4*)(hp + (size_t)b * 1024 + kc + half * 32);
#pragma unroll
                    for (int i = 0; i < 8; i++) {
                        float4 v = h4[i];
                        int k = half * 32 + i * 4;
                        hs[(k+0)*64 + b] = v.x; hs[(k+1)*64 + b] = v.y;
                        hs[(k+2)*64 + b] = v.z; hs[(k+3)*64 + b] = v.w;
                    }
                }
                __syncthreads();
#pragma unroll 16
                for (int k = 0; k < 64; k++) {
                    float4 wv = *(const float4*)&ws[(kc + k) * 32 + c0];
                    float4 hv = *(const float4*)&hs[k * 64 + b0];
                    acc[0][0] += hv.x * wv.x; acc[0][1] += hv.x * wv.y;
                    acc[0][2] += hv.x * wv.z; acc[0][3] += hv.x * wv.w;
                    acc[1][0] += hv.y * wv.x; acc[1][1] += hv.y * wv.y;
                    acc[1][2] += hv.y * wv.z; acc[1][3] += hv.y * wv.w;
                    acc[2][0] += hv.z * wv.x; acc[2][1] += hv.z * wv.y;
                    acc[2][2] += hv.z * wv.z; acc[2][3] += hv.z * wv.w;
                    acc[3][0] += hv.w * wv.x; acc[3][1] += hv.w * wv.y;
                    acc[3][2] += hv.w * wv.z; acc[3][3] += hv.w * wv.w;
                }
                __syncthreads();
            }
        }

        // gates -> smem (+ precomputed x-projection incl. biases)
        const float* xpt = xp + (size_t)t * BATCH * GATES;
#pragma unroll
        for (int bi = 0; bi < 4; bi++) {
            int b = b0 + bi;
#pragma unroll
            for (int ci = 0; ci < 4; ci++) {
                int c = c0 + ci;
                int col = ((c >> 3) << 10) + j0 + (c & 7);
                gsm[b * 33 + c] = acc[bi][ci] + xpt[(size_t)b * GATES + col];
            }
        }
        __syncthreads();

        // elementwise gate math + state update
        float* hw = (mode == 0) ? hist + (size_t)t * BH
                                : hist + (size_t)(t & 1) * BH;
#pragma unroll
        for (int q = tid; q < 512; q += 128) {
            int b  = q & 63;
            int jj = q >> 6;
            float gi = gsm[b * 33 + jj];
            float gf = gsm[b * 33 + 8  + jj];
            float gg = gsm[b * 33 + 16 + jj];
            float go = gsm[b * 33 + 24 + jj];
            float ii = 1.f / (1.f + expf(-gi));
            float ff = 1.f / (1.f + expf(-gf));
            float gt = tanhf(gg);
            float oo = 1.f / (1.f + expf(-go));
            float cn = ff * cst[jj * 64 + b] + ii * gt;
            float hn = oo * tanhf(cn);
            cst[jj * 64 + b] = cn;
            hw[(size_t)b * HID + j0 + jj] = hn;
            if (t == SEQL - 1) {
                out_h[(size_t)b * HID + j0 + jj] = hn;
                out_c[(size_t)b * HID + j0 + jj] = cn;
            }
        }
        gridbar(nblk);
    }
}

// ---------------- launch ----------------------------------------------------
extern "C" void kernel_launch(void* const* d_in, const int* in_sizes, int n_in,
                              void* d_out, int out_size)
{
    const int*   seq  = (const int*)d_in[0];
    const float* emb  = (const float*)d_in[1];
    const float* wih0 = (const float*)d_in[2];
    const float* whh0 = (const float*)d_in[3];
    const float* bih0 = (const float*)d_in[4];
    const float* bhh0 = (const float*)d_in[5];
    const float* wih1 = (const float*)d_in[6];
    const float* whh1 = (const float*)d_in[7];
    const float* bih1 = (const float*)d_in[8];
    const float* bhh1 = (const float*)d_in[9];
    float* out = (float*)d_out;

    float *xp, *ys, *hb;
    cudaGetSymbolAddress((void**)&xp, g_xp);
    cudaGetSymbolAddress((void**)&ys, g_ys);
    cudaGetSymbolAddress((void**)&hb, g_hb);

    cudaFuncSetAttribute(lstm_rec, cudaFuncAttributeMaxDynamicSharedMemorySize, REC_SMEM);

    dim3 gg(GATES / 128, MROWS / 128);   // (32, 128)

    // layer 0: x-projection (with embedding gather), then recurrence.
    // out layout: [h0 | h1 | c0 | c1], each 64x1024
    sgemm_xp<<<gg, 256>>>(emb, seq, wih0, bih0, bhh0, xp);
    lstm_rec<<<128, 128, REC_SMEM>>>(xp, whh0, ys, 0, out, out + 2 * BH);

    // layer 1: x-projection from ys, then recurrence.
    sgemm_xp<<<gg, 256>>>(ys, nullptr, wih1, bih1, bhh1, xp);
    lstm_rec<<<128, 128, REC_SMEM>>>(xp, whh1, hb, 1, out + BH, out + 3 * BH);
}

// round 2
// speedup vs baseline: 2.1610x; 2.1610x over previous
#include <cuda_runtime.h>
#include <math.h>
#include <stdint.h>

#define SEQL 256
#define BATCH 64
#define HID 1024
#define GATES 4096
#define MROWS (SEQL*BATCH)      // 16384
#define BH (BATCH*HID)          // 65536

// ---------------- scratch (device globals; no cudaMalloc allowed) ----------
__device__ float g_xp[(size_t)MROWS * GATES];   // 256 MB: x-projection for one layer
__device__ float g_ys[(size_t)SEQL * BH];       // 64 MB: layer-0 h history
__device__ float g_hb[2 * BH];                  // layer-1 h ping-pong
__device__ volatile unsigned g_bar_gen;
__device__ unsigned g_bar_cnt;

// ---------------- helpers ---------------------------------------------------
__device__ __forceinline__ uint32_t f2tf32(float x) {
    uint32_t r; asm("cvt.rna.tf32.f32 %0, %1;" : "=r"(r) : "f"(x)); return r;
}
__device__ __forceinline__ void mma8(float* d, const uint32_t* a, const uint32_t* b) {
    asm volatile(
        "mma.sync.aligned.m16n8k8.row.col.f32.tf32.tf32.f32 "
        "{%0,%1,%2,%3},{%4,%5,%6,%7},{%8,%9},{%0,%1,%2,%3};"
        : "+f"(d[0]), "+f"(d[1]), "+f"(d[2]), "+f"(d[3])
        : "r"(a[0]), "r"(a[1]), "r"(a[2]), "r"(a[3]), "r"(b[0]), "r"(b[1]));
}
__device__ __forceinline__ void cpa16(uint32_t s, const void* g) {
    asm volatile("cp.async.cg.shared.global [%0], [%1], 16;" :: "r"(s), "l"(g));
}
#define CP_COMMIT() asm volatile("cp.async.commit_group;")
#define CP_WAIT(n)  asm volatile("cp.async.wait_group %0;" :: "n"(n))

__device__ __forceinline__ float sigf(float x) { return __fdividef(1.f, 1.f + __expf(-x)); }
__device__ __forceinline__ float tanhfast(float x) { return __fdividef(2.f, 1.f + __expf(-2.f * x)) - 1.f; }

// ---------------- grid barrier (all 128 blocks resident, 1/SM) --------------
__device__ __forceinline__ void gridbar(unsigned nblk) {
    __threadfence();
    __syncthreads();
    if (threadIdx.x == 0) {
        unsigned gen = g_bar_gen;
        if (atomicAdd(&g_bar_cnt, 1u) == nblk - 1u) {
            atomicExch(&g_bar_cnt, 0u);
            __threadfence();
            g_bar_gen = gen + 1u;
        } else {
            while (g_bar_gen == gen) { __nanosleep(32); }
            __threadfence();
        }
    }
    __syncthreads();
}

// ---------------- tf32 SGEMM: C[M][4096] = gather(A)[M][1024] @ W^T + b1 + b2
// block 128x128, k-chunk 32, 256 threads (8 warps, 2x4), warp tile 64x32
#define PA 136
__global__ __launch_bounds__(256) void sgemm_xp(
    const float* __restrict__ A, const int* __restrict__ gidx,
    const float* __restrict__ W,
    const float* __restrict__ b1, const float* __restrict__ b2,
    float* __restrict__ C)
{
    __shared__ uint32_t As[32 * PA];
    __shared__ uint32_t Ws[32 * PA];
    const int bn = blockIdx.x * 128;
    const int bm = blockIdx.y * 128;
    const int tid = threadIdx.x;
    const int warp = tid >> 5, lane = tid & 31;
    const int g = lane >> 2, tig = lane & 3;
    const int wm = warp >> 2, wn = warp & 3;

    float acc[4][4][4];
#pragma unroll
    for (int mi = 0; mi < 4; mi++)
#pragma unroll
        for (int ni = 0; ni < 4; ni++)
#pragma unroll
            for (int r = 0; r < 4; r++) acc[mi][ni][r] = 0.f;

    for (int kc = 0; kc < 1024; kc += 32) {
#pragma unroll
        for (int rep = 0; rep < 4; rep++) {
            int q = tid + rep * 256;
            int row = q >> 3;      // 0..127
            int c4  = q & 7;       // 0..7 -> k = 4*c4..+3
            int sw  = c4 << 2;
            int arow = gidx ? gidx[bm + row] : (bm + row);
            float4 v = *(const float4*)(A + (size_t)arow * 1024 + kc + c4 * 4);
            As[(c4*4+0)*PA + (row ^ sw)] = f2tf32(v.x);
            As[(c4*4+1)*PA + (row ^ sw)] = f2tf32(v.y);
            As[(c4*4+2)*PA + (row ^ sw)] = f2tf32(v.z);
            As[(c4*4+3)*PA + (row ^ sw)] = f2tf32(v.w);
            float4 w = *(const float4*)(W + (size_t)(bn + row) * 1024 + kc + c4 * 4);
            Ws[(c4*4+0)*PA + (row ^ sw)] = f2tf32(w.x);
            Ws[(c4*4+1)*PA + (row ^ sw)] = f2tf32(w.y);
            Ws[(c4*4+2)*PA + (row ^ sw)] = f2tf32(w.z);
            Ws[(c4*4+3)*PA + (row ^ sw)] = f2tf32(w.w);
        }
        __syncthreads();
#pragma unroll
        for (int kk = 0; kk < 4; kk++) {
            int klo = kk * 8 + tig, khi = klo + 4;
            int swlo = ((klo >> 2) & 7) << 2;
            int swhi = ((khi >> 2) & 7) << 2;
            uint32_t a[4][4], b[4][2];
#pragma unroll
            for (int mi = 0; mi < 4; mi++) {
                int mr = wm * 64 + mi * 16 + g;
                a[mi][0] = As[klo * PA + (mr ^ swlo)];
                a[mi][1] = As[klo * PA + ((mr + 8) ^ swlo)];
                a[mi][2] = As[khi * PA + (mr ^ swhi)];
                a[mi][3] = As[khi * PA + ((mr + 8) ^ swhi)];
            }
#pragma unroll
            for (int ni = 0; ni < 4; ni++) {
                int nc = wn * 32 + ni * 8 + g;
                b[ni][0] = Ws[klo * PA + (nc ^ swlo)];
                b[ni][1] = Ws[khi * PA + (nc ^ swhi)];
            }
#pragma unroll
            for (int mi = 0; mi < 4; mi++)
#pragma unroll
                for (int ni = 0; ni < 4; ni++)
                    mma8(acc[mi][ni], a[mi], b[ni]);
        }
        __syncthreads();
    }

    // epilogue: + b1 + b2
#pragma unroll
    for (int ni = 0; ni < 4; ni++) {
        int nc = bn + wn * 32 + ni * 8 + 2 * tig;
        float bia0 = b1[nc] + b2[nc];
        float bia1 = b1[nc + 1] + b2[nc + 1];
#pragma unroll
        for (int mi = 0; mi < 4; mi++) {
            int mr = bm + wm * 64 + mi * 16 + g;
            *(float2*)(C + (size_t)mr * GATES + nc) =
                make_float2(acc[mi][ni][0] + bia0, acc[mi][ni][1] + bia1);
            *(float2*)(C + (size_t)(mr + 8) * GATES + nc) =
                make_float2(acc[mi][ni][2] + bia0, acc[mi][ni][3] + bia1);
        }
    }
}

// ---------------- persistent LSTM recurrence (tf32 mma) ---------------------
// 128 blocks x 128 threads. Block owns 8 hidden cols j0..j0+7 (x4 gates = 32
// gate cols). ws (tf32 weights, [1024][PW]) in SMEM for all 256 steps.
// h chunk (64 k) double-buffered via cp.async, layout hs[b][k] stride PH.
// c-state entirely in registers (4 per thread).
#define PW 40
#define PH 68
#define REC_SMEM ((1024*PW + 2*64*PH) * 4)

__global__ __launch_bounds__(128, 1) void lstm_rec(
    const float* __restrict__ xp, const float* __restrict__ whh,
    float* hist, int mode, float* __restrict__ out_h, float* __restrict__ out_c)
{
    extern __shared__ float sm[];
    uint32_t* ws = (uint32_t*)sm;              // [1024][PW] tf32
    float* hs = sm + 1024 * PW;                // [2][64][PH]
    const uint32_t hs_u32 = (uint32_t)__cvta_generic_to_shared(hs);

    const int tid = threadIdx.x;
    const int warp = tid >> 5, lane = tid & 31;
    const int g = lane >> 2, tig = lane & 3;
    const int j0 = blockIdx.x * 8;
    const int mrow = warp * 16 + g;            // batch rows: mrow, mrow+8

    // preload weights (tf32) once
    {
        int c = tid & 31;                               // gate-col 0..31
        int kq = tid >> 5;                              // k quarter
        int wrow = ((c >> 3) << 10) + j0 + (c & 7);     // global gate col
        const float4* w4 = (const float4*)(whh + (size_t)wrow * 1024);
        for (int k4 = kq * 64; k4 < kq * 64 + 64; k4++) {
            float4 v = w4[k4];
            int k = 4 * k4;
            ws[(k+0)*PW + c] = f2tf32(v.x);
            ws[(k+1)*PW + c] = f2tf32(v.y);
            ws[(k+2)*PW + c] = f2tf32(v.z);
            ws[(k+3)*PW + c] = f2tf32(v.w);
        }
    }
    __syncthreads();

    float cst[4] = {0.f, 0.f, 0.f, 0.f};   // c-state: [ri*2+ci]
    const int sb = tid & 63;                // staging batch row
    const int skh = (tid >> 6) * 32;        // staging k half

    for (int t = 0; t < SEQL; t++) {
        // prefetch xp (biases already folded in): 8 x float2
        const float* xpt = xp + (size_t)t * BATCH * GATES;
        float2 xv[8];
#pragma unroll
        for (int gi = 0; gi < 4; gi++)
#pragma unroll
            for (int ri = 0; ri < 2; ri++) {
                int b = mrow + ri * 8;
                xv[gi*2+ri] = *(const float2*)(xpt + (size_t)b * GATES + gi * 1024 + j0 + 2 * tig);
            }

        float acc[4][4];
#pragma unroll
        for (int ni = 0; ni < 4; ni++)
#pragma unroll
            for (int r = 0; r < 4; r++) acc[ni][r] = 0.f;

        if (t > 0) {
            const float* hp = (mode == 0) ? hist + (size_t)(t-1) * BH
                                          : hist + (size_t)((t-1) & 1) * BH;
            // stage chunk 0
            {
                uint32_t s = hs_u32 + (sb * PH + skh) * 4;
                const float* gp = hp + (size_t)sb * 1024 + skh;
#pragma unroll
                for (int i = 0; i < 8; i++) cpa16(s + 16 * i, gp + 4 * i);
                CP_COMMIT();
            }
            for (int kc = 0; kc < 16; kc++) {
                if (kc < 15) {
                    int buf = (kc + 1) & 1;
                    uint32_t s = hs_u32 + (buf * 64 * PH + sb * PH + skh) * 4;
                    const float* gp = hp + (size_t)sb * 1024 + (kc + 1) * 64 + skh;
#pragma unroll
                    for (int i = 0; i < 8; i++) cpa16(s + 16 * i, gp + 4 * i);
                    CP_COMMIT();
                    CP_WAIT(1);
                } else {
                    CP_WAIT(0);
                }
                __syncthreads();
                const float* hb = hs + (kc & 1) * 64 * PH;
                const int kg = kc * 64;
#pragma unroll
                for (int kk = 0; kk < 8; kk++) {
                    int klo = kk * 8 + tig, khi = klo + 4;
                    uint32_t a[4];
                    a[0] = __float_as_uint(hb[mrow * PH + klo]);
                    a[1] = __float_as_uint(hb[(mrow + 8) * PH + klo]);
                    a[2] = __float_as_uint(hb[mrow * PH + khi]);
                    a[3] = __float_as_uint(hb[(mrow + 8) * PH + khi]);
#pragma unroll
                    for (int ni = 0; ni < 4; ni++) {
                        uint32_t b[2];
                        int nc = ni * 8 + g;
                        b[0] = ws[(kg + klo) * PW + nc];
                        b[1] = ws[(kg + khi) * PW + nc];
                        mma8(acc[ni], a, b);
                    }
                }
                __syncthreads();
            }
        }

        // gate math fully in registers; acc[gate][ri*2+ci]
        float* hw = (mode == 0) ? hist + (size_t)t * BH
                                : hist + (size_t)(t & 1) * BH;
#pragma unroll
        for (int ri = 0; ri < 2; ri++)
#pragma unroll
            for (int ci = 0; ci < 2; ci++) {
                int r = ri * 2 + ci;
                int b = mrow + ri * 8;
                int jj = 2 * tig + ci;
                float xi = ci ? xv[0*2+ri].y : xv[0*2+ri].x;
                float xf = ci ? xv[1*2+ri].y : xv[1*2+ri].x;
                float xg = ci ? xv[2*2+ri].y : xv[2*2+ri].x;
                float xo = ci ? xv[3*2+ri].y : xv[3*2+ri].x;
                float ii = sigf(acc[0][r] + xi);
                float ff = sigf(acc[1][r] + xf);
                float gg = tanhfast(acc[2][r] + xg);
                float oo = sigf(acc[3][r] + xo);
                float cn = ff * cst[r] + ii * gg;
                float hn = oo * tanhfast(cn);
                cst[r] = cn;
                hw[(size_t)b * HID + j0 + jj] = hn;
                if (t == SEQL - 1) {
                    out_h[(size_t)b * HID + j0 + jj] = hn;
                    out_c[(size_t)b * HID + j0 + jj] = cn;
                }
            }
        gridbar(gridDim.x);
    }
}

// ---------------- launch ----------------------------------------------------
extern "C" void kernel_launch(void* const* d_in, const int* in_sizes, int n_in,
                              void* d_out, int out_size)
{
    const int*   seq  = (const int*)d_in[0];
    const float* emb  = (const float*)d_in[1];
    const float* wih0 = (const float*)d_in[2];
    const float* whh0 = (const float*)d_in[3];
    const float* bih0 = (const float*)d_in[4];
    const float* bhh0 = (const float*)d_in[5];
    const float* wih1 = (const float*)d_in[6];
    const float* whh1 = (const float*)d_in[7];
    const float* bih1 = (const float*)d_in[8];
    const float* bhh1 = (const float*)d_in[9];
    float* out = (float*)d_out;

    float *xp, *ys, *hb;
    cudaGetSymbolAddress((void**)&xp, g_xp);
    cudaGetSymbolAddress((void**)&ys, g_ys);
    cudaGetSymbolAddress((void**)&hb, g_hb);

    cudaFuncSetAttribute(lstm_rec, cudaFuncAttributeMaxDynamicSharedMemorySize, REC_SMEM);

    dim3 gg(GATES / 128, MROWS / 128);   // (32, 128)

    // out layout: [h0 | h1 | c0 | c1], each 64x1024
    sgemm_xp<<<gg, 256>>>(emb, seq, wih0, bih0, bhh0, xp);
    lstm_rec<<<128, 128, REC_SMEM>>>(xp, whh0, ys, 0, out, out + 2 * BH);

    sgemm_xp<<<gg, 256>>>(ys, nullptr, wih1, bih1, bhh1, xp);
    lstm_rec<<<128, 128, REC_SMEM>>>(xp, whh1, hb, 1, out + BH, out + 3 * BH);
}

// round 3
// speedup vs baseline: 2.4056x; 1.1132x over previous
#include <cuda_runtime.h>
#include <math.h>
#include <stdint.h>

#define SEQL 256
#define BATCH 64
#define HID 1024
#define GATES 4096
#define MROWS (SEQL*BATCH)      // 16384
#define BH (BATCH*HID)          // 65536

// ---------------- scratch (device globals; no cudaMalloc allowed) ----------
__device__ float g_xp[(size_t)MROWS * GATES];   // 256 MB: x-projection for one layer
__device__ float g_ys[(size_t)SEQL * BH];       // 64 MB: layer-0 h history
__device__ float g_hb[2 * BH];                  // layer-1 h ping-pong
__device__ volatile unsigned g_bar_gen;
__device__ unsigned g_bar_cnt;

// ---------------- helpers ---------------------------------------------------
__device__ __forceinline__ uint32_t f2tf32(float x) {
    uint32_t r; asm("cvt.rna.tf32.f32 %0, %1;" : "=r"(r) : "f"(x)); return r;
}
__device__ __forceinline__ void mma8(float* d, const uint32_t* a, const uint32_t* b) {
    asm volatile(
        "mma.sync.aligned.m16n8k8.row.col.f32.tf32.tf32.f32 "
        "{%0,%1,%2,%3},{%4,%5,%6,%7},{%8,%9},{%0,%1,%2,%3};"
        : "+f"(d[0]), "+f"(d[1]), "+f"(d[2]), "+f"(d[3])
        : "r"(a[0]), "r"(a[1]), "r"(a[2]), "r"(a[3]), "r"(b[0]), "r"(b[1]));
}
__device__ __forceinline__ void cpa16(uint32_t s, const void* g) {
    asm volatile("cp.async.cg.shared.global [%0], [%1], 16;" :: "r"(s), "l"(g));
}
#define CP_COMMIT() asm volatile("cp.async.commit_group;")
#define CP_WAIT(n)  asm volatile("cp.async.wait_group %0;" :: "n"(n))

__device__ __forceinline__ float sigf(float x) { return __fdividef(1.f, 1.f + __expf(-x)); }
__device__ __forceinline__ float tanhfast(float x) { return __fdividef(2.f, 1.f + __expf(-2.f * x)) - 1.f; }

// ---------------- grid barrier (all 128 blocks resident, 1/SM) --------------
__device__ __forceinline__ void gridbar(unsigned nblk) {
    __threadfence();
    __syncthreads();
    if (threadIdx.x == 0) {
        unsigned gen = g_bar_gen;
        if (atomicAdd(&g_bar_cnt, 1u) == nblk - 1u) {
            atomicExch(&g_bar_cnt, 0u);
            __threadfence();
            g_bar_gen = gen + 1u;
        } else {
            while (g_bar_gen == gen) { __nanosleep(32); }
            __threadfence();
        }
    }
    __syncthreads();
}

// ---------------- tf32 SGEMM v3: cp.async 2-stage pipelined ------------------
// C[M][4096] = gather(A)[M][1024] @ W^T + b1 + b2
// block 128x128, k-chunk 32, 256 threads (8 warps 2x4), warp tile 64x32.
// SMEM: 2 stages x [As 128x32 | Ws 128x32] fp32, XOR swizzle: elem (m,k) at
// m*32 + (k ^ ((m&7)<<2)). Fragments cvt.rna'd to tf32 in registers.
#define STG 8192   // floats per stage (As 4096 + Ws 4096)
__global__ __launch_bounds__(256, 2) void sgemm_xp(
    const float* __restrict__ A, const int* __restrict__ gidx,
    const float* __restrict__ W,
    const float* __restrict__ b1, const float* __restrict__ b2,
    float* __restrict__ C)
{
    extern __shared__ float smf[];
    const uint32_t smem_b = (uint32_t)__cvta_generic_to_shared(smf);
    const int bn = blockIdx.x * 128;
    const int bm = blockIdx.y * 128;
    const int tid = threadIdx.x;
    const int warp = tid >> 5, lane = tid & 31;
    const int g = lane >> 2, tig = lane & 3;
    const int wm = warp >> 2, wn = warp & 3;

    // per-thread copy assignment: 4 (m,j) pairs for A and W each
    int cm[4]; int cj[4]; int arow[4]; uint32_t adst[4], wdst[4];
#pragma unroll
    for (int rep = 0; rep < 4; rep++) {
        int q = tid + rep * 256;
        int m = q >> 3, j = q & 7;
        cm[rep] = m; cj[rep] = j;
        arow[rep] = gidx ? gidx[bm + m] : (bm + m);
        uint32_t off = (uint32_t)(m * 32 + ((4 * j) ^ ((m & 7) << 2)));
        adst[rep] = smem_b + off * 4;
        wdst[rep] = smem_b + (off + 4096) * 4;
    }

    float acc[4][4][4];
#pragma unroll
    for (int mi = 0; mi < 4; mi++)
#pragma unroll
        for (int ni = 0; ni < 4; ni++)
#pragma unroll
            for (int r = 0; r < 4; r++) acc[mi][ni][r] = 0.f;

    // prologue: stage chunk 0 into buffer 0
#pragma unroll
    for (int rep = 0; rep < 4; rep++) {
        cpa16(adst[rep], A + (size_t)arow[rep] * 1024 + 4 * cj[rep]);
        cpa16(wdst[rep], W + (size_t)(bn + cm[rep]) * 1024 + 4 * cj[rep]);
    }
    CP_COMMIT();

    const int swz = g << 2;
    for (int c = 0; c < 32; c++) {
        if (c + 1 < 32) {
            uint32_t so = (uint32_t)(((c + 1) & 1) * STG) * 4;
            int kc = (c + 1) * 32;
#pragma unroll
            for (int rep = 0; rep < 4; rep++) {
                cpa16(adst[rep] + so, A + (size_t)arow[rep] * 1024 + kc + 4 * cj[rep]);
                cpa16(wdst[rep] + so, W + (size_t)(bn + cm[rep]) * 1024 + kc + 4 * cj[rep]);
            }
        }
        CP_COMMIT();
        CP_WAIT(1);
        __syncthreads();

        const float* As = smf + (c & 1) * STG;
        const float* Ws = As + 4096;
#pragma unroll
        for (int kk = 0; kk < 4; kk++) {
            int kl = (kk * 8 + tig) ^ swz;
            int kh = (kk * 8 + tig + 4) ^ swz;
            uint32_t a[4][4], b[4][2];
#pragma unroll
            for (int mi = 0; mi < 4; mi++) {
                int base = (wm * 64 + mi * 16 + g) * 32;
                a[mi][0] = f2tf32(As[base + kl]);
                a[mi][1] = f2tf32(As[base + 256 + kl]);
                a[mi][2] = f2tf32(As[base + kh]);
                a[mi][3] = f2tf32(As[base + 256 + kh]);
            }
#pragma unroll
            for (int ni = 0; ni < 4; ni++) {
                int nb = (wn * 32 + ni * 8 + g) * 32;
                b[ni][0] = f2tf32(Ws[nb + kl]);
                b[ni][1] = f2tf32(Ws[nb + kh]);
            }
#pragma unroll
            for (int mi = 0; mi < 4; mi++)
#pragma unroll
                for (int ni = 0; ni < 4; ni++)
                    mma8(acc[mi][ni], a[mi], b[ni]);
        }
        __syncthreads();
    }

    // epilogue: + b1 + b2
#pragma unroll
    for (int ni = 0; ni < 4; ni++) {
        int nc = bn + wn * 32 + ni * 8 + 2 * tig;
        float bia0 = b1[nc] + b2[nc];
        float bia1 = b1[nc + 1] + b2[nc + 1];
#pragma unroll
        for (int mi = 0; mi < 4; mi++) {
            int mr = bm + wm * 64 + mi * 16 + g;
            *(float2*)(C + (size_t)mr * GATES + nc) =
                make_float2(acc[mi][ni][0] + bia0, acc[mi][ni][1] + bia1);
            *(float2*)(C + (size_t)(mr + 8) * GATES + nc) =
                make_float2(acc[mi][ni][2] + bia0, acc[mi][ni][3] + bia1);
        }
    }
}
#define SGEMM_SMEM (2 * STG * 4)

// ---------------- persistent LSTM recurrence (tf32 mma) ---------------------
// (unchanged from R2)
#define PW 40
#define PH 68
#define REC_SMEM ((1024*PW + 2*64*PH) * 4)

__global__ __launch_bounds__(128, 1) void lstm_rec(
    const float* __restrict__ xp, const float* __restrict__ whh,
    float* hist, int mode, float* __restrict__ out_h, float* __restrict__ out_c)
{
    extern __shared__ float sm[];
    uint32_t* ws = (uint32_t*)sm;              // [1024][PW] tf32
    float* hs = sm + 1024 * PW;                // [2][64][PH]
    const uint32_t hs_u32 = (uint32_t)__cvta_generic_to_shared(hs);

    const int tid = threadIdx.x;
    const int warp = tid >> 5, lane = tid & 31;
    const int g = lane >> 2, tig = lane & 3;
    const int j0 = blockIdx.x * 8;
    const int mrow = warp * 16 + g;            // batch rows: mrow, mrow+8

    // preload weights (tf32) once
    {
        int c = tid & 31;                               // gate-col 0..31
        int kq = tid >> 5;                              // k quarter
        int wrow = ((c >> 3) << 10) + j0 + (c & 7);     // global gate col
        const float4* w4 = (const float4*)(whh + (size_t)wrow * 1024);
        for (int k4 = kq * 64; k4 < kq * 64 + 64; k4++) {
            float4 v = w4[k4];
            int k = 4 * k4;
            ws[(k+0)*PW + c] = f2tf32(v.x);
            ws[(k+1)*PW + c] = f2tf32(v.y);
            ws[(k+2)*PW + c] = f2tf32(v.z);
            ws[(k+3)*PW + c] = f2tf32(v.w);
        }
    }
    __syncthreads();

    float cst[4] = {0.f, 0.f, 0.f, 0.f};   // c-state: [ri*2+ci]
    const int sb = tid & 63;                // staging batch row
    const int skh = (tid >> 6) * 32;        // staging k half

    for (int t = 0; t < SEQL; t++) {
        const float* xpt = xp + (size_t)t * BATCH * GATES;
        float2 xv[8];
#pragma unroll
        for (int gi = 0; gi < 4; gi++)
#pragma unroll
            for (int ri = 0; ri < 2; ri++) {
                int b = mrow + ri * 8;
                xv[gi*2+ri] = *(const float2*)(xpt + (size_t)b * GATES + gi * 1024 + j0 + 2 * tig);
            }

        float acc[4][4];
#pragma unroll
        for (int ni = 0; ni < 4; ni++)
#pragma unroll
            for (int r = 0; r < 4; r++) acc[ni][r] = 0.f;

        if (t > 0) {
            const float* hp = (mode == 0) ? hist + (size_t)(t-1) * BH
                                          : hist + (size_t)((t-1) & 1) * BH;
            {
                uint32_t s = hs_u32 + (sb * PH + skh) * 4;
                const float* gp = hp + (size_t)sb * 1024 + skh;
#pragma unroll
                for (int i = 0; i < 8; i++) cpa16(s + 16 * i, gp + 4 * i);
                CP_COMMIT();
            }
            for (int kc = 0; kc < 16; kc++) {
                if (kc < 15) {
                    int buf = (kc + 1) & 1;
                    uint32_t s = hs_u32 + (buf * 64 * PH + sb * PH + skh) * 4;
                    const float* gp = hp + (size_t)sb * 1024 + (kc + 1) * 64 + skh;
#pragma unroll
                    for (int i = 0; i < 8; i++) cpa16(s + 16 * i, gp + 4 * i);
                    CP_COMMIT();
                    CP_WAIT(1);
                } else {
                    CP_WAIT(0);
                }
                __syncthreads();
                const float* hb = hs + (kc & 1) * 64 * PH;
                const int kg = kc * 64;
#pragma unroll
                for (int kk = 0; kk < 8; kk++) {
                    int klo = kk * 8 + tig, khi = klo + 4;
                    uint32_t a[4];
                    a[0] = __float_as_uint(hb[mrow * PH + klo]);
                    a[1] = __float_as_uint(hb[(mrow + 8) * PH + klo]);
                    a[2] = __float_as_uint(hb[mrow * PH + khi]);
                    a[3] = __float_as_uint(hb[(mrow + 8) * PH + khi]);
#pragma unroll
                    for (int ni = 0; ni < 4; ni++) {
                        uint32_t b[2];
                        int nc = ni * 8 + g;
                        b[0] = ws[(kg + klo) * PW + nc];
                        b[1] = ws[(kg + khi) * PW + nc];
                        mma8(acc[ni], a, b);
                    }
                }
                __syncthreads();
            }
        }

        float* hw = (mode == 0) ? hist + (size_t)t * BH
                                : hist + (size_t)(t & 1) * BH;
#pragma unroll
        for (int ri = 0; ri < 2; ri++)
#pragma unroll
            for (int ci = 0; ci < 2; ci++) {
                int r = ri * 2 + ci;
                int b = mrow + ri * 8;
                int jj = 2 * tig + ci;
                float xi = ci ? xv[0*2+ri].y : xv[0*2+ri].x;
                float xf = ci ? xv[1*2+ri].y : xv[1*2+ri].x;
                float xg = ci ? xv[2*2+ri].y : xv[2*2+ri].x;
                float xo = ci ? xv[3*2+ri].y : xv[3*2+ri].x;
                float ii = sigf(acc[0][r] + xi);
                float ff = sigf(acc[1][r] + xf);
                float gg = tanhfast(acc[2][r] + xg);
                float oo = sigf(acc[3][r] + xo);
                float cn = ff * cst[r] + ii * gg;
                float hn = oo * tanhfast(cn);
                cst[r] = cn;
                hw[(size_t)b * HID + j0 + jj] = hn;
                if (t == SEQL - 1) {
                    out_h[(size_t)b * HID + j0 + jj] = hn;
                    out_c[(size_t)b * HID + j0 + jj] = cn;
                }
            }
        gridbar(gridDim.x);
    }
}

// ---------------- launch ----------------------------------------------------
extern "C" void kernel_launch(void* const* d_in, const int* in_sizes, int n_in,
                              void* d_out, int out_size)
{
    const int*   seq  = (const int*)d_in[0];
    const float* emb  = (const float*)d_in[1];
    const float* wih0 = (const float*)d_in[2];
    const float* whh0 = (const float*)d_in[3];
    const float* bih0 = (const float*)d_in[4];
    const float* bhh0 = (const float*)d_in[5];
    const float* wih1 = (const float*)d_in[6];
    const float* whh1 = (const float*)d_in[7];
    const float* bih1 = (const float*)d_in[8];
    const float* bhh1 = (const float*)d_in[9];
    float* out = (float*)d_out;

    float *xp, *ys, *hb;
    cudaGetSymbolAddress((void**)&xp, g_xp);
    cudaGetSymbolAddress((void**)&ys, g_ys);
    cudaGetSymbolAddress((void**)&hb, g_hb);

    cudaFuncSetAttribute(sgemm_xp, cudaFuncAttributeMaxDynamicSharedMemorySize, SGEMM_SMEM);
    cudaFuncSetAttribute(lstm_rec, cudaFuncAttributeMaxDynamicSharedMemorySize, REC_SMEM);

    dim3 gg(GATES / 128, MROWS / 128);   // (32, 128)

    // out layout: [h0 | h1 | c0 | c1], each 64x1024
    sgemm_xp<<<gg, 256, SGEMM_SMEM>>>(emb, seq, wih0, bih0, bhh0, xp);
    lstm_rec<<<128, 128, REC_SMEM>>>(xp, whh0, ys, 0, out, out + 2 * BH);

    sgemm_xp<<<gg, 256, SGEMM_SMEM>>>(ys, nullptr, wih1, bih1, bhh1, xp);
    lstm_rec<<<128, 128, REC_SMEM>>>(xp, whh1, hb, 1, out + BH, out + 3 * BH);
}